// round 2
// baseline (speedup 1.0000x reference)
#include <cuda_runtime.h>
#include <cuda_fp16.h>
#include <cstdint>

// ---------------- problem constants ----------------
#define D_M   8192      // B*S
#define D_K   4096
#define D_N   11008

#define BM    128
#define BN    256
#define BK    64        // 64 fp16 = 128B rows (SW128 atom)
#define KITERS (D_K / BK)   // 64
#define NS    4             // pipeline stages

static constexpr int MT = D_M / BM;   // 64
static constexpr int NT = D_N / BN;   // 43

static constexpr int A_TILE_BYTES = BM * BK * 2;  // 16384
static constexpr int B_TILE_BYTES = BN * BK * 2;  // 32768

// smem layout
static constexpr int SM_FULL  = 0;                    // NS * 8
static constexpr int SM_EMPTY = SM_FULL + NS * 8;     // 32
static constexpr int SM_BIAS  = 128;                  // BN floats = 1024B
static constexpr int SM_A     = 2048;                              // 1024-aligned
static constexpr int SM_B     = SM_A + NS * A_TILE_BYTES;          // 67584
static constexpr int SMEM_TOTAL = SM_B + NS * B_TILE_BYTES;        // 198656

// ---------------- scratch (tiled, pre-swizzled fp16) ----------------
__device__ __align__(1024) __half g_xt[(size_t)D_M * D_K];   // 64 MiB
__device__ __align__(1024) __half g_wt[(size_t)D_N * D_K];   // 86 MiB

// ---------------- PTX helpers ----------------
__device__ __forceinline__ uint32_t smem_u32(const void* p) {
    uint32_t a;
    asm("{ .reg .u64 t; cvta.to.shared.u64 t, %1; cvt.u32.u64 %0, t; }" : "=r"(a) : "l"(p));
    return a;
}
__device__ __forceinline__ uint32_t elect_one() {
    uint32_t p;
    asm volatile("{ .reg .pred p; elect.sync _|p, 0xFFFFFFFF; selp.b32 %0, 1, 0, p; }" : "=r"(p));
    return p;
}
#define MBAR_INIT(a, cnt) \
    asm volatile("mbarrier.init.shared.b64 [%0], %1;" :: "r"(a), "r"((uint32_t)(cnt)) : "memory")
#define MBAR_EXPECT_TX(a, b) \
    asm volatile("mbarrier.arrive.expect_tx.shared.b64 _, [%0], %1;" :: "r"(a), "r"((uint32_t)(b)) : "memory")
#define MBAR_ARRIVE(a) \
    asm volatile("mbarrier.arrive.shared.b64 _, [%0];" :: "r"(a) : "memory")

#define MBAR_WAIT(a, ph) do {                                                   \
    uint32_t _m = (a); uint32_t _p = (uint32_t)(ph); uint32_t _d;               \
    asm volatile("{ .reg .pred p; mbarrier.try_wait.parity.acquire.cta.shared::cta.b64 p, [%1], %2; selp.b32 %0,1,0,p; }" \
        : "=r"(_d) : "r"(_m), "r"(_p) : "memory");                              \
    if (!_d) { asm volatile("{ .reg .pred P1; WL%=:\n\t"                        \
        "mbarrier.try_wait.parity.acquire.cta.shared::cta.b64 P1, [%0], %1, 0x989680;\n\t" \
        "@P1 bra.uni WD%=;\n\t bra.uni WL%=;\n\t WD%=: }"                       \
        :: "r"(_m), "r"(_p) : "memory"); }                                      \
} while (0)

__device__ __forceinline__ void bulk_g2s(uint32_t dst, const void* src, uint32_t bytes, uint32_t mbar) {
    asm volatile("cp.async.bulk.shared::cta.global.mbarrier::complete_tx::bytes [%0], [%1], %2, [%3];"
        :: "r"(dst), "l"(src), "r"(bytes), "r"(mbar) : "memory");
}

__device__ __forceinline__ void ldmx4(uint32_t& r0, uint32_t& r1, uint32_t& r2, uint32_t& r3, uint32_t a) {
    asm volatile("ldmatrix.sync.aligned.m8n8.x4.shared.b16 {%0,%1,%2,%3}, [%4];"
        : "=r"(r0), "=r"(r1), "=r"(r2), "=r"(r3) : "r"(a));
}

__device__ __forceinline__ void mma16816(float* c, const uint32_t* a, uint32_t b0, uint32_t b1) {
    asm volatile("mma.sync.aligned.m16n8k16.row.col.f32.f16.f16.f32 "
        "{%0,%1,%2,%3}, {%4,%5,%6,%7}, {%8,%9}, {%0,%1,%2,%3};"
        : "+f"(c[0]), "+f"(c[1]), "+f"(c[2]), "+f"(c[3])
        : "r"(a[0]), "r"(a[1]), "r"(a[2]), "r"(a[3]), "r"(b0), "r"(b1));
}

__device__ __forceinline__ uint32_t swz(uint32_t off) { return off ^ ((off >> 3) & 0x70); }

// ---------------- converter kernels (write pre-swizzled tiles) ----------------
__global__ void conv_x_kernel(const float* __restrict__ x, __half* __restrict__ xt) {
    int tile = blockIdx.x;            // tile = mt*KITERS + kc
    int mt = tile / KITERS, kc = tile % KITERS;
    const float* src = x + (size_t)mt * BM * D_K + (size_t)kc * BK;
    char* dst = (char*)(xt + (size_t)tile * (BM * BK));
    for (int i = threadIdx.x; i < BM * BK / 2; i += blockDim.x) {
        int row = i >> 5;             // 32 half2 per 64-elem row
        int c2  = i & 31;
        float2 v = *(const float2*)(src + (size_t)row * D_K + c2 * 2);
        __half2 h = __floats2half2_rn(v.x, v.y);
        *(__half2*)(dst + swz(row * 128 + c2 * 4)) = h;
    }
}

__global__ void conv_w_kernel(const int* __restrict__ qw, const float* __restrict__ zp_p,
                              __half* __restrict__ wt) {
    float zp = *zp_p;
    int tile = blockIdx.x;            // tile = nt*KITERS + kc
    int nt = tile / KITERS, kc = tile % KITERS;
    const int* src = qw + (size_t)nt * BN * D_K + (size_t)kc * BK;
    char* dst = (char*)(wt + (size_t)tile * (BN * BK));
    for (int i = threadIdx.x; i < BN * BK / 2; i += blockDim.x) {
        int row = i >> 5;
        int c2  = i & 31;
        int2 q = *(const int2*)(src + (size_t)row * D_K + c2 * 2);
        __half2 h = __floats2half2_rn((float)q.x - zp, (float)q.y - zp);
        *(__half2*)(dst + swz(row * 128 + c2 * 4)) = h;
    }
}

// ---------------- main GEMM kernel ----------------
// 512 threads, 16 warps in 4(M) x 4(N) grid; warp tile 32 x 64.
__global__ void __launch_bounds__(512, 1)
gemm_kernel(const float* __restrict__ scale_p, const float* __restrict__ bias,
            float* __restrict__ out) {
    extern __shared__ char smem[];
    uint32_t sb = smem_u32(smem);
    int tid = threadIdx.x, wid = tid >> 5, lane = tid & 31;
    int wm = wid & 3;          // 0..3  (M)
    int wn = wid >> 2;         // 0..3  (N)

    // tile decode with M-group swizzle for L2 reuse
    const int GROUP = 16;
    int bid = blockIdx.x;
    int tpg = GROUP * NT;
    int g = bid / tpg, r = bid % tpg;
    int mt = g * GROUP + (r % GROUP);
    int nt = r / GROUP;

    if (tid == 0) {
        for (int s = 0; s < NS; s++) {
            MBAR_INIT(sb + SM_FULL  + s * 8, 1);
            MBAR_INIT(sb + SM_EMPTY + s * 8, 16);
        }
    }
    for (int i = tid; i < BN; i += 512)
        ((float*)(smem + SM_BIAS))[i] = bias[(size_t)nt * BN + i];
    __syncthreads();

    const char* asrc = (const char*)g_xt + (size_t)mt * KITERS * A_TILE_BYTES;
    const char* bsrc = (const char*)g_wt + (size_t)nt * KITERS * B_TILE_BYTES;

    // prologue: fill all NS stages
    if (tid == 0) {
        for (int s = 0; s < NS; s++) {
            MBAR_EXPECT_TX(sb + SM_FULL + s * 8, A_TILE_BYTES + B_TILE_BYTES);
            bulk_g2s(sb + SM_A + s * A_TILE_BYTES, asrc + (size_t)s * A_TILE_BYTES,
                     A_TILE_BYTES, sb + SM_FULL + s * 8);
            bulk_g2s(sb + SM_B + s * B_TILE_BYTES, bsrc + (size_t)s * B_TILE_BYTES,
                     B_TILE_BYTES, sb + SM_FULL + s * 8);
        }
    }

    // per-lane ldmatrix addressing components
    int lrow = (lane & 7) + ((lane >> 3) & 1) * 8;   // 0..15 within 16-row block
    int lcb  = (lane >> 4) * 16;                     // 0 or 16 bytes (k half)

    float acc[2][4][2][4];    // [mi][g16][sub][4]
    #pragma unroll
    for (int i = 0; i < 2; i++)
        #pragma unroll
        for (int j = 0; j < 4; j++)
            #pragma unroll
            for (int k = 0; k < 2; k++)
                #pragma unroll
                for (int l = 0; l < 4; l++) acc[i][j][k][l] = 0.f;

    for (int it = 0; it < KITERS; ++it) {
        int s = it & (NS - 1);
        int u = it >> 2;   // NS == 4
        MBAR_WAIT(sb + SM_FULL + s * 8, u & 1);

        uint32_t abase = sb + SM_A + s * A_TILE_BYTES;
        uint32_t bbase = sb + SM_B + s * B_TILE_BYTES;

        #pragma unroll
        for (int kk = 0; kk < 4; kk++) {           // four k16 steps in BK=64
            uint32_t afr[2][4];
            #pragma unroll
            for (int mi = 0; mi < 2; mi++) {
                uint32_t off = (uint32_t)(wm * 32 + mi * 16 + lrow) * 128 + kk * 32 + lcb;
                ldmx4(afr[mi][0], afr[mi][1], afr[mi][2], afr[mi][3], abase + swz(off));
            }
            uint32_t bfr[4][4];
            #pragma unroll
            for (int gg = 0; gg < 4; gg++) {
                uint32_t off = (uint32_t)(wn * 64 + gg * 16 + lrow) * 128 + kk * 32 + lcb;
                ldmx4(bfr[gg][0], bfr[gg][1], bfr[gg][2], bfr[gg][3], bbase + swz(off));
            }
            #pragma unroll
            for (int mi = 0; mi < 2; mi++)
                #pragma unroll
                for (int gg = 0; gg < 4; gg++) {
                    mma16816(acc[mi][gg][0], afr[mi], bfr[gg][0], bfr[gg][2]);
                    mma16816(acc[mi][gg][1], afr[mi], bfr[gg][1], bfr[gg][3]);
                }
        }

        if (elect_one()) MBAR_ARRIVE(sb + SM_EMPTY + s * 8);

        if (tid == 0 && it + NS < KITERS) {
            MBAR_WAIT(sb + SM_EMPTY + s * 8, u & 1);
            int nx = it + NS;
            MBAR_EXPECT_TX(sb + SM_FULL + s * 8, A_TILE_BYTES + B_TILE_BYTES);
            bulk_g2s(sb + SM_A + s * A_TILE_BYTES, asrc + (size_t)nx * A_TILE_BYTES,
                     A_TILE_BYTES, sb + SM_FULL + s * 8);
            bulk_g2s(sb + SM_B + s * B_TILE_BYTES, bsrc + (size_t)nx * B_TILE_BYTES,
                     B_TILE_BYTES, sb + SM_FULL + s * 8);
        }
    }

    // ---- epilogue ----
    float scl = *scale_p;
    const float* bs = (const float*)(smem + SM_BIAS);
    int qrow = lane >> 2;          // 0..7
    int qcol = (lane & 3) * 2;     // 0,2,4,6
    #pragma unroll
    for (int mi = 0; mi < 2; mi++) {
        #pragma unroll
        for (int gg = 0; gg < 4; gg++) {
            #pragma unroll
            for (int sub = 0; sub < 2; sub++) {
                int ncol = wn * 64 + gg * 16 + sub * 8 + qcol;       // local in BN
                int m0   = mt * BM + wm * 32 + mi * 16 + qrow;
                size_t og = (size_t)m0 * D_N + (size_t)nt * BN + ncol;
                float b0 = bs[ncol], b1 = bs[ncol + 1];
                float2 v0, v1;
                v0.x = fmaf(scl, acc[mi][gg][sub][0], b0);
                v0.y = fmaf(scl, acc[mi][gg][sub][1], b1);
                v1.x = fmaf(scl, acc[mi][gg][sub][2], b0);
                v1.y = fmaf(scl, acc[mi][gg][sub][3], b1);
                *(float2*)(out + og) = v0;
                *(float2*)(out + og + (size_t)8 * D_N) = v1;
            }
        }
    }
}

// ---------------- launch ----------------
extern "C" void kernel_launch(void* const* d_in, const int* in_sizes, int n_in,
                              void* d_out, int out_size) {
    const float* x     = (const float*)d_in[0];
    const int*   qw    = (const int*)d_in[1];
    const float* scale = (const float*)d_in[2];
    const float* zp    = (const float*)d_in[3];
    const float* bias  = (const float*)d_in[4];
    float* out = (float*)d_out;

    __half* xt; cudaGetSymbolAddress((void**)&xt, g_xt);
    __half* wt; cudaGetSymbolAddress((void**)&wt, g_wt);

    cudaFuncSetAttribute(gemm_kernel, cudaFuncAttributeMaxDynamicSharedMemorySize, SMEM_TOTAL);

    conv_x_kernel<<<MT * KITERS, 256>>>(x, xt);
    conv_w_kernel<<<NT * KITERS, 256>>>(qw, zp, wt);
    gemm_kernel<<<MT * NT, 512, SMEM_TOTAL>>>(scale, bias, out);
}